// round 1
// baseline (speedup 1.0000x reference)
#include <cuda_runtime.h>

#define B_ 8
#define C_ 256
#define H_ 128
#define W_ 128
#define HW_ (H_*W_)
#define ROWS 4          // pixel rows per conv thread
#define CG 2            // channel groups (conv split across blocks)
#define CPG (C_/CG)     // 128 channels per group

// Partial conv sums: [group][b][h][w] as float2 (px_part, py_part). 2 MB scratch.
__device__ float2 g_part[CG * B_ * H_ * W_];

// ---------------------------------------------------------------------------
// Kernel 1: offset conv (Conv2d C_->2, k=3, pad=1), partial over channel group.
// Grid: B_*(H_/ROWS)*CG = 512 blocks, 128 threads (one per column).
// ---------------------------------------------------------------------------
__global__ __launch_bounds__(128) void conv_kernel(const float* __restrict__ x,
                                                   const float* __restrict__ wc) {
    const int w = threadIdx.x;                 // 0..127 (column)
    int bx = blockIdx.x;
    const int g  = bx & (CG - 1); bx >>= 1;    // channel group
    const int hb = bx & 31;       bx >>= 5;    // row tile (H_/ROWS = 32)
    const int b  = bx;                         // batch
    const int h0 = hb * ROWS;
    const int c0 = g * CPG;

    __shared__ float sw0[CPG * 9];             // weights, out channel 0
    __shared__ float sw1[CPG * 9];             // weights, out channel 1
    __shared__ float sx[ROWS + 2][W_ + 4];     // x tile: rows h0-1..h0+ROWS, cols -1..128

    // Stage this group's weights (contiguous per out-channel): wc[o][c][3][3]
    for (int i = w; i < CPG * 9; i += 128) {
        sw0[i] = wc[c0 * 9 + i];
        sw1[i] = wc[C_ * 9 + c0 * 9 + i];
    }
    // Zero-pad halo columns once (never overwritten inside the loop)
    if (w < ROWS + 2) { sx[w][0] = 0.f; sx[w][W_ + 1] = 0.f; }

    float ax[ROWS], ay[ROWS];
#pragma unroll
    for (int r = 0; r < ROWS; r++) { ax[r] = 0.f; ay[r] = 0.f; }

    const float* xb = x + (size_t)(b * C_ + c0) * HW_;

#pragma unroll 1
    for (int c = 0; c < CPG; c++) {
        __syncthreads();                       // protect previous iter's reads
        const float* xc = xb + c * HW_;
#pragma unroll
        for (int r = 0; r < ROWS + 2; r++) {   // stage 6 rows, zero-pad edges
            const int hr = h0 - 1 + r;
            float v = 0.f;
            if (hr >= 0 && hr < H_) v = xc[hr * W_ + w];
            sx[r][w + 1] = v;
        }
        __syncthreads();

        float wv0[9], wv1[9];
#pragma unroll
        for (int t = 0; t < 9; t++) { wv0[t] = sw0[c * 9 + t]; wv1[t] = sw1[c * 9 + t]; }

        float xr[ROWS + 2][3];
#pragma unroll
        for (int r = 0; r < ROWS + 2; r++)
#pragma unroll
            for (int j = 0; j < 3; j++) xr[r][j] = sx[r][w + j];

#pragma unroll
        for (int r = 0; r < ROWS; r++)
#pragma unroll
            for (int kh = 0; kh < 3; kh++)
#pragma unroll
                for (int kw = 0; kw < 3; kw++) {
                    const float v = xr[r + kh][kw];
                    ax[r] = fmaf(wv0[kh * 3 + kw], v, ax[r]);
                    ay[r] = fmaf(wv1[kh * 3 + kw], v, ay[r]);
                }
    }

#pragma unroll
    for (int r = 0; r < ROWS; r++)
        g_part[((g * B_ + b) * H_ + (h0 + r)) * W_ + w] = make_float2(ax[r], ay[r]);
}

// ---------------------------------------------------------------------------
// Kernel 2: combine partials -> (px,py), clip, bilinear gather over all C.
// Grid: B_*H_ = 1024 blocks, 128 threads (one per column).
// ---------------------------------------------------------------------------
__global__ __launch_bounds__(128) void sample_kernel(const float* __restrict__ x,
                                                     const float* __restrict__ bc,
                                                     float* __restrict__ out) {
    const int w = threadIdx.x;
    const int h = blockIdx.x & (H_ - 1);
    const int b = blockIdx.x >> 7;
    const int pix = (b * H_ + h) * W_ + w;

    const float2 p0 = g_part[pix];
    const float2 p1 = g_part[B_ * HW_ + pix];

    float px = (float)h + p0.x + p1.x + bc[0];
    float py = (float)w + p0.y + p1.y + bc[1];
    px = fminf(fmaxf(px, 0.f), (float)(H_ - 2));
    py = fminf(fmaxf(py, 0.f), (float)(W_ - 2));

    const float fx = floorf(px), fy = floorf(py);
    const float dx = px - fx,    dy = py - fy;
    // g_lt:(qx0,qy0) g_lb:(qx0,qy1) g_rt:(qx1,qy0) g_rb:(qx1,qy1)
    const float w00 = (1.f - dx) * (1.f - dy);
    const float w01 = (1.f - dx) * dy;
    const float w10 = dx * (1.f - dy);
    const float w11 = dx * dy;

    const int qx = (int)fx, qy = (int)fy;
    const float* xp = x   + (size_t)b * C_ * HW_ + qx * W_ + qy;
    float*       op = out + (size_t)b * C_ * HW_ + h * W_ + w;

#pragma unroll 4
    for (int c = 0; c < C_; c++) {
        const float* p = xp + c * HW_;
        const float v00 = __ldg(p);
        const float v01 = __ldg(p + 1);
        const float v10 = __ldg(p + W_);
        const float v11 = __ldg(p + W_ + 1);
        op[c * HW_] = w00 * v00 + w01 * v01 + w10 * v10 + w11 * v11;
    }
}

// ---------------------------------------------------------------------------
extern "C" void kernel_launch(void* const* d_in, const int* in_sizes, int n_in,
                              void* d_out, int out_size) {
    const float* x  = (const float*)d_in[0];   // [8,256,128,128]
    const float* wc = (const float*)d_in[1];   // [2,256,3,3]
    const float* bc = (const float*)d_in[2];   // [2]
    float* out = (float*)d_out;                // [8,256,128,128,1]

    conv_kernel<<<B_ * (H_ / ROWS) * CG, 128>>>(x, wc);
    sample_kernel<<<B_ * H_, 128>>>(x, bc, out);
}

// round 2
// speedup vs baseline: 1.2653x; 1.2653x over previous
#include <cuda_runtime.h>

#define B_ 8
#define C_ 256
#define H_ 128
#define W_ 128
#define HW_ (H_*W_)
#define ROWS 4          // pixel rows per conv thread
#define CG 4            // conv channel groups
#define CPG (C_/CG)     // 64 channels per group
#define CSPLIT 4        // sampler channel splits
#define CPS (C_/CSPLIT) // 64 channels per sampler block

// Partial conv sums: [group][b][h][w] as float2 (px_part, py_part). 4 MB scratch.
__device__ float2 g_part[CG * B_ * H_ * W_];

// ---------------------------------------------------------------------------
// Kernel 1: offset conv partials. Grid: B_*32*CG = 1024 blocks, 128 threads.
// Double-buffered smem, register prefetch, ONE barrier per channel.
// ---------------------------------------------------------------------------
__global__ __launch_bounds__(128) void conv_kernel(const float* __restrict__ x,
                                                   const float* __restrict__ wc) {
    const int t = threadIdx.x;                 // 0..127 = column
    int bx = blockIdx.x;
    const int g  = bx & (CG - 1); bx >>= 2;
    const int hb = bx & 31;       bx >>= 5;
    const int b  = bx;
    const int h0 = hb * ROWS;
    const int c0 = g * CPG;

    __shared__ float  sw0[CPG * 9];
    __shared__ float  sw1[CPG * 9];
    __shared__ float4 sx[2][6 * 32];           // [buf][row*32 + colgroup]

    for (int i = t; i < CPG * 9; i += 128) {
        sw0[i] = wc[c0 * 9 + i];
        sw1[i] = wc[C_ * 9 + c0 * 9 + i];
    }

    const float* xb = x + (size_t)(b * C_ + c0) * HW_;

    // float4 staging slots: 6 rows * 32 groups = 192; thread t -> slot t, 128+t
    const int r0 = t >> 5,        q0 = (t & 31) * 4;
    const int r1 = (128 + t) >> 5, q1 = (t & 31) * 4;
    const int hr0 = h0 - 1 + r0;
    const int hr1 = h0 - 1 + r1;
    const bool v0 = (hr0 >= 0 && hr0 < H_);
    const bool v1 = (t < 64) && (hr1 >= 0 && hr1 < H_);
    const float4 z4 = make_float4(0.f, 0.f, 0.f, 0.f);

    // prefetch channel 0
    float4 a0 = v0 ? *(const float4*)(xb + hr0 * W_ + q0) : z4;
    float4 a1 = v1 ? *(const float4*)(xb + hr1 * W_ + q1) : z4;
    sx[0][t] = a0;
    if (t < 64) sx[0][128 + t] = a1;
    __syncthreads();

    float ax[ROWS] = {0.f, 0.f, 0.f, 0.f};
    float ay[ROWS] = {0.f, 0.f, 0.f, 0.f};
    const int w = t;

#pragma unroll 1
    for (int c = 0; c < CPG; c++) {
        const int cur = c & 1;
        if (c + 1 < CPG) {                      // issue next channel's loads early
            const float* xc = xb + (c + 1) * HW_;
            a0 = v0 ? *(const float4*)(xc + hr0 * W_ + q0) : z4;
            a1 = v1 ? *(const float4*)(xc + hr1 * W_ + q1) : z4;
        }

        float wv0[9], wv1[9];
#pragma unroll
        for (int k = 0; k < 9; k++) { wv0[k] = sw0[c * 9 + k]; wv1[k] = sw1[c * 9 + k]; }

        const float* sb = (const float*)sx[cur];
        float xv[6][3];
#pragma unroll
        for (int r = 0; r < 6; r++) {
            const float* row = sb + r * 128;
            xv[r][1] = row[w];
            xv[r][0] = (w > 0)   ? row[w - 1] : 0.f;
            xv[r][2] = (w < 127) ? row[w + 1] : 0.f;
        }

#pragma unroll
        for (int r = 0; r < ROWS; r++)
#pragma unroll
            for (int kh = 0; kh < 3; kh++)
#pragma unroll
                for (int kw = 0; kw < 3; kw++) {
                    const float v = xv[r + kh][kw];
                    ax[r] = fmaf(wv0[kh * 3 + kw], v, ax[r]);
                    ay[r] = fmaf(wv1[kh * 3 + kw], v, ay[r]);
                }

        if (c + 1 < CPG) {                      // fill the other buffer
            sx[1 - cur][t] = a0;
            if (t < 64) sx[1 - cur][128 + t] = a1;
        }
        __syncthreads();                        // single barrier per channel
    }

#pragma unroll
    for (int r = 0; r < ROWS; r++)
        g_part[((g * B_ + b) * H_ + (h0 + r)) * W_ + w] = make_float2(ax[r], ay[r]);
}

// ---------------------------------------------------------------------------
// Kernel 2: combine partials -> (px,py), clip, bilinear gather.
// Grid: B_*H_*CSPLIT = 4096 blocks, 128 threads.
// ---------------------------------------------------------------------------
__global__ __launch_bounds__(128) void sample_kernel(const float* __restrict__ x,
                                                     const float* __restrict__ bc,
                                                     float* __restrict__ out) {
    const int w = threadIdx.x;
    int bx = blockIdx.x;
    const int s = bx & (CSPLIT - 1); bx >>= 2;
    const int h = bx & (H_ - 1);
    const int b = bx >> 7;
    const int pix = (b * H_ + h) * W_ + w;

    float ox = bc[0], oy = bc[1];
#pragma unroll
    for (int g = 0; g < CG; g++) {
        const float2 p = g_part[g * B_ * HW_ + pix];
        ox += p.x; oy += p.y;
    }

    float px = (float)h + ox;
    float py = (float)w + oy;
    px = fminf(fmaxf(px, 0.f), (float)(H_ - 2));
    py = fminf(fmaxf(py, 0.f), (float)(W_ - 2));

    const float fx = floorf(px), fy = floorf(py);
    const float dx = px - fx,    dy = py - fy;
    const float w00 = (1.f - dx) * (1.f - dy);
    const float w01 = (1.f - dx) * dy;
    const float w10 = dx * (1.f - dy);
    const float w11 = dx * dy;

    const int qx = (int)fx, qy = (int)fy;
    const float* xp = x   + ((size_t)b * C_ + s * CPS) * HW_ + qx * W_ + qy;
    float*       op = out + ((size_t)b * C_ + s * CPS) * HW_ + h * W_ + w;

#pragma unroll 8
    for (int c = 0; c < CPS; c++) {
        const float* p = xp + c * HW_;
        const float v00 = __ldg(p);
        const float v01 = __ldg(p + 1);
        const float v10 = __ldg(p + W_);
        const float v11 = __ldg(p + W_ + 1);
        op[c * HW_] = fmaf(w00, v00, fmaf(w01, v01, fmaf(w10, v10, w11 * v11)));
    }
}

// ---------------------------------------------------------------------------
extern "C" void kernel_launch(void* const* d_in, const int* in_sizes, int n_in,
                              void* d_out, int out_size) {
    const float* x  = (const float*)d_in[0];   // [8,256,128,128]
    const float* wc = (const float*)d_in[1];   // [2,256,3,3]
    const float* bc = (const float*)d_in[2];   // [2]
    float* out = (float*)d_out;                // [8,256,128,128,1]

    conv_kernel<<<B_ * (H_ / ROWS) * CG, 128>>>(x, wc);
    sample_kernel<<<B_ * H_ * CSPLIT, 128>>>(x, bc, out);
}

// round 3
// speedup vs baseline: 1.3212x; 1.0442x over previous
#include <cuda_runtime.h>

#define B_ 8
#define C_ 256
#define H_ 128
#define W_ 128
#define HW_ (H_*W_)
#define NPIX (B_*HW_)

#define CG16 16          // conv channel groups
#define CPG16 (C_/CG16)  // 16 channels per group
#define RT 16            // output rows per conv block (4 warps * 4 rows)

#define CSPLIT 4
#define CPS (C_/CSPLIT)

// conv partials [group][b*HW] and merged offsets [b*HW]
__device__ float2 g_part[CG16 * NPIX];   // 16.8 MB
__device__ float2 g_off[NPIX];           // 1 MB

__device__ __forceinline__ unsigned long long pack2(float v) {
    unsigned long long r;
    asm("mov.b64 %0, {%1, %1};" : "=l"(r) : "f"(v));
    return r;
}
__device__ __forceinline__ void ffma2(unsigned long long& d,
                                      unsigned long long a,
                                      unsigned long long b) {
    asm("fma.rn.f32x2 %0, %1, %2, %0;" : "+l"(d) : "l"(a), "l"(b));
}
__device__ __forceinline__ void unpack2(unsigned long long v, float& lo, float& hi) {
    asm("mov.b64 {%0, %1}, %2;" : "=f"(lo), "=f"(hi) : "l"(v));
}

// ---------------------------------------------------------------------------
// Kernel 1: offset conv partials. No smem-x, no inner barriers.
// Each thread: 4x4 output tile, both out-channels packed as f32x2.
// Warp spans all 128 columns (lane L -> cols 4L..4L+3); W-edges are zero-pad.
// Grid: B_ * (H_/RT) * CG16 = 1024 blocks, 128 threads.
// ---------------------------------------------------------------------------
__global__ __launch_bounds__(128) void conv_kernel(const float* __restrict__ x,
                                                   const float* __restrict__ wc) {
    const int lane = threadIdx.x & 31;
    const int wrp  = threadIdx.x >> 5;
    int bx = blockIdx.x;
    const int g  = bx & 15; bx >>= 4;
    const int hb = bx & 7;  bx >>= 3;
    const int b  = bx;
    const int h0   = hb * RT + wrp * 4;   // first output row of this warp
    const int c0   = g * CPG16;
    const int col0 = lane * 4;

    __shared__ float2 swp[CPG16 * 9];     // interleaved (w_ch0, w_ch1)
    for (int i = threadIdx.x; i < CPG16 * 9; i += 128)
        swp[i] = make_float2(wc[c0 * 9 + i], wc[C_ * 9 + c0 * 9 + i]);
    __syncthreads();                      // only barrier in the kernel

    unsigned long long acc[4][4];
#pragma unroll
    for (int r = 0; r < 4; r++)
#pragma unroll
        for (int j = 0; j < 4; j++) acc[r][j] = 0ull;

    const float* xb = x + (size_t)(b * C_ + c0) * HW_;

#pragma unroll 1
    for (int c = 0; c < CPG16; c++) {
        const float* xc = xb + c * HW_;
        float4 f[6];
#pragma unroll
        for (int r = 0; r < 6; r++) {
            const int hr = h0 - 1 + r;
            if (hr >= 0 && hr < H_) f[r] = *(const float4*)(xc + hr * W_ + col0);
            else                    f[r] = make_float4(0.f, 0.f, 0.f, 0.f);
        }

        float colv[6][6];
#pragma unroll
        for (int r = 0; r < 6; r++) {
            float lh = __shfl_up_sync(0xffffffffu, f[r].w, 1);
            float rh = __shfl_down_sync(0xffffffffu, f[r].x, 1);
            if (lane == 0)  lh = 0.f;     // col -1  (zero pad)
            if (lane == 31) rh = 0.f;     // col 128 (zero pad)
            colv[r][0] = lh;   colv[r][1] = f[r].x; colv[r][2] = f[r].y;
            colv[r][3] = f[r].z; colv[r][4] = f[r].w; colv[r][5] = rh;
        }

        unsigned long long wp[9];
#pragma unroll
        for (int k = 0; k < 9; k++)
            wp[k] = *(const unsigned long long*)&swp[c * 9 + k];

#pragma unroll
        for (int ri = 0; ri < 6; ri++)
#pragma unroll
            for (int ci = 0; ci < 6; ci++) {
                const unsigned long long v2 = pack2(colv[ri][ci]);
#pragma unroll
                for (int kh = 0; kh < 3; kh++) {
                    const int rr = ri - kh;
                    if (rr < 0 || rr > 3) continue;
#pragma unroll
                    for (int kw = 0; kw < 3; kw++) {
                        const int j = ci - kw;
                        if (j < 0 || j > 3) continue;
                        ffma2(acc[rr][j], wp[kh * 3 + kw], v2);
                    }
                }
            }
    }

    float2* gp = g_part + (size_t)g * NPIX + b * HW_;
#pragma unroll
    for (int rr = 0; rr < 4; rr++)
#pragma unroll
        for (int j = 0; j < 4; j++) {
            float axv, ayv;
            unpack2(acc[rr][j], axv, ayv);
            gp[(h0 + rr) * W_ + col0 + j] = make_float2(axv, ayv);
        }
}

// ---------------------------------------------------------------------------
// Kernel 1.5: merge the 16 partials into one offset buffer.
// ---------------------------------------------------------------------------
__global__ __launch_bounds__(256) void reduce_kernel() {
    const int i = blockIdx.x * 256 + threadIdx.x;
    float ox = 0.f, oy = 0.f;
#pragma unroll
    for (int g = 0; g < CG16; g++) {
        const float2 p = g_part[(size_t)g * NPIX + i];
        ox += p.x; oy += p.y;
    }
    g_off[i] = make_float2(ox, oy);
}

// ---------------------------------------------------------------------------
// Kernel 2: bilinear gather with merged (float2) corner loads.
// Grid: B_*H_*CSPLIT = 4096 blocks, 128 threads.
// ---------------------------------------------------------------------------
__global__ __launch_bounds__(128) void sample_kernel(const float* __restrict__ x,
                                                     const float* __restrict__ bc,
                                                     float* __restrict__ out) {
    const int w = threadIdx.x;
    int bx = blockIdx.x;
    const int s = bx & (CSPLIT - 1); bx >>= 2;
    const int h = bx & (H_ - 1);
    const int b = bx >> 7;
    const int pix = (b * H_ + h) * W_ + w;

    const float2 o = g_off[pix];
    float px = (float)h + o.x + bc[0];
    float py = (float)w + o.y + bc[1];
    px = fminf(fmaxf(px, 0.f), (float)(H_ - 2));
    py = fminf(fmaxf(py, 0.f), (float)(W_ - 2));

    const float fx = floorf(px), fy = floorf(py);
    const float dx = px - fx,    dy = py - fy;
    const float w00 = (1.f - dx) * (1.f - dy);
    const float w01 = (1.f - dx) * dy;
    const float w10 = dx * (1.f - dy);
    const float w11 = dx * dy;

    const int qx = (int)fx, qy = (int)fy;
    const int e  = qy & ~1;               // 8B-aligned column
    const bool odd = (qy & 1);

    const float* rb = x   + ((size_t)b * C_ + s * CPS) * HW_ + qx * W_ + e;
    float*       op = out + ((size_t)b * C_ + s * CPS) * HW_ + h * W_ + w;

#pragma unroll 8
    for (int c = 0; c < CPS; c++) {
        const float2 f0 = __ldg((const float2*)rb);          // row qx:   e, e+1
        const float2 f1 = __ldg((const float2*)(rb + W_));   // row qx+1: e, e+1
        float v00, v01, v10, v11;
        if (odd) {
            v00 = f0.y; v01 = __ldg(rb + 2);
            v10 = f1.y; v11 = __ldg(rb + W_ + 2);
        } else {
            v00 = f0.x; v01 = f0.y;
            v10 = f1.x; v11 = f1.y;
        }
        *op = fmaf(w00, v00, fmaf(w01, v01, fmaf(w10, v10, w11 * v11)));
        rb += HW_; op += HW_;
    }
}

// ---------------------------------------------------------------------------
extern "C" void kernel_launch(void* const* d_in, const int* in_sizes, int n_in,
                              void* d_out, int out_size) {
    const float* x  = (const float*)d_in[0];   // [8,256,128,128]
    const float* wc = (const float*)d_in[1];   // [2,256,3,3]
    const float* bc = (const float*)d_in[2];   // [2]
    float* out = (float*)d_out;                // [8,256,128,128,1]

    conv_kernel<<<B_ * (H_ / RT) * CG16, 128>>>(x, wc);
    reduce_kernel<<<NPIX / 256, 256>>>();
    sample_kernel<<<B_ * H_ * CSPLIT, 128>>>(x, bc, out);
}

// round 4
// speedup vs baseline: 1.5498x; 1.1730x over previous
#include <cuda_runtime.h>

#define B_ 8
#define C_ 256
#define H_ 128
#define W_ 128
#define HW_ (H_*W_)
#define NPIX (B_*HW_)

#define CG16 16          // conv channel groups
#define CPG16 (C_/CG16)  // 16 channels per group
#define RT 16            // output rows per conv block (4 warps * 4 rows)

#define CSPLIT 4
#define CPS (C_/CSPLIT)

// conv partials [group][b*HW] and merged offsets [b*HW]
__device__ float2 g_part[CG16 * NPIX];   // 16.8 MB
__device__ float2 g_off[NPIX];           // 1 MB

__device__ __forceinline__ unsigned long long pack2(float v) {
    unsigned long long r;
    asm("mov.b64 %0, {%1, %1};" : "=l"(r) : "f"(v));
    return r;
}
__device__ __forceinline__ void ffma2(unsigned long long& d,
                                      unsigned long long a,
                                      unsigned long long b) {
    asm("fma.rn.f32x2 %0, %1, %2, %0;" : "+l"(d) : "l"(a), "l"(b));
}
__device__ __forceinline__ void unpack2(unsigned long long v, float& lo, float& hi) {
    asm("mov.b64 {%0, %1}, %2;" : "=f"(lo), "=f"(hi) : "l"(v));
}

// ---------------------------------------------------------------------------
// Kernel 1: offset conv partials. No smem-x, no inner barriers, register
// double-buffering across channels (prefetch next channel's 6 float4 rows).
// Each thread: 4x4 output tile, both out-channels packed as f32x2.
// Grid: B_ * (H_/RT) * CG16 = 1024 blocks, 128 threads.
// ---------------------------------------------------------------------------
__global__ __launch_bounds__(128) void conv_kernel(const float* __restrict__ x,
                                                   const float* __restrict__ wc) {
    const int lane = threadIdx.x & 31;
    const int wrp  = threadIdx.x >> 5;
    int bx = blockIdx.x;
    const int g  = bx & 15; bx >>= 4;
    const int hb = bx & 7;  bx >>= 3;
    const int b  = bx;
    const int h0   = hb * RT + wrp * 4;   // first output row of this warp
    const int c0   = g * CPG16;
    const int col0 = lane * 4;

    __shared__ float2 swp[CPG16 * 9];     // interleaved (w_ch0, w_ch1)
    for (int i = threadIdx.x; i < CPG16 * 9; i += 128)
        swp[i] = make_float2(wc[c0 * 9 + i], wc[C_ * 9 + c0 * 9 + i]);
    __syncthreads();                      // only barrier in the kernel

    unsigned long long acc[4][4];
#pragma unroll
    for (int r = 0; r < 4; r++)
#pragma unroll
        for (int j = 0; j < 4; j++) acc[r][j] = 0ull;

    const float* xb = x + (size_t)(b * C_ + c0) * HW_;
    const float4 z4 = make_float4(0.f, 0.f, 0.f, 0.f);

    // row validity is channel-invariant
    bool rv[6]; int roff[6];
#pragma unroll
    for (int r = 0; r < 6; r++) {
        const int hr = h0 - 1 + r;
        rv[r]   = (hr >= 0 && hr < H_);
        roff[r] = hr * W_ + col0;
    }

    float4 f[6];
#pragma unroll
    for (int r = 0; r < 6; r++) f[r] = rv[r] ? *(const float4*)(xb + roff[r]) : z4;

#pragma unroll 1
    for (int c = 0; c < CPG16; c++) {
        float4 fn[6];
        if (c + 1 < CPG16) {              // prefetch next channel early
            const float* xc = xb + (c + 1) * HW_;
#pragma unroll
            for (int r = 0; r < 6; r++) fn[r] = rv[r] ? *(const float4*)(xc + roff[r]) : z4;
        }

        float colv[6][6];
#pragma unroll
        for (int r = 0; r < 6; r++) {
            float lh = __shfl_up_sync(0xffffffffu, f[r].w, 1);
            float rh = __shfl_down_sync(0xffffffffu, f[r].x, 1);
            if (lane == 0)  lh = 0.f;     // col -1  (zero pad)
            if (lane == 31) rh = 0.f;     // col 128 (zero pad)
            colv[r][0] = lh;   colv[r][1] = f[r].x; colv[r][2] = f[r].y;
            colv[r][3] = f[r].z; colv[r][4] = f[r].w; colv[r][5] = rh;
        }

        unsigned long long wp[9];
#pragma unroll
        for (int k = 0; k < 9; k++)
            wp[k] = *(const unsigned long long*)&swp[c * 9 + k];

#pragma unroll
        for (int ri = 0; ri < 6; ri++)
#pragma unroll
            for (int ci = 0; ci < 6; ci++) {
                const unsigned long long v2 = pack2(colv[ri][ci]);
#pragma unroll
                for (int kh = 0; kh < 3; kh++) {
                    const int rr = ri - kh;
                    if (rr < 0 || rr > 3) continue;
#pragma unroll
                    for (int kw = 0; kw < 3; kw++) {
                        const int j = ci - kw;
                        if (j < 0 || j > 3) continue;
                        ffma2(acc[rr][j], wp[kh * 3 + kw], v2);
                    }
                }
            }

        if (c + 1 < CPG16) {
#pragma unroll
            for (int r = 0; r < 6; r++) f[r] = fn[r];
        }
    }

    float2* gp = g_part + (size_t)g * NPIX + b * HW_;
#pragma unroll
    for (int rr = 0; rr < 4; rr++)
#pragma unroll
        for (int j = 0; j < 4; j++) {
            float axv, ayv;
            unpack2(acc[rr][j], axv, ayv);
            gp[(h0 + rr) * W_ + col0 + j] = make_float2(axv, ayv);
        }
}

// ---------------------------------------------------------------------------
// Kernel 1.5: merge the 16 partials into one offset buffer.
// ---------------------------------------------------------------------------
__global__ __launch_bounds__(256) void reduce_kernel() {
    const int i = blockIdx.x * 256 + threadIdx.x;
    float ox = 0.f, oy = 0.f;
#pragma unroll
    for (int g = 0; g < CG16; g++) {
        const float2 p = g_part[(size_t)g * NPIX + i];
        ox += p.x; oy += p.y;
    }
    g_off[i] = make_float2(ox, oy);
}

// ---------------------------------------------------------------------------
// Kernel 2: bilinear gather (r2 form: 4 scalar __ldg, no divergence).
// Grid: B_*H_*CSPLIT = 4096 blocks, 128 threads.
// ---------------------------------------------------------------------------
__global__ __launch_bounds__(128) void sample_kernel(const float* __restrict__ x,
                                                     const float* __restrict__ bc,
                                                     float* __restrict__ out) {
    const int w = threadIdx.x;
    int bx = blockIdx.x;
    const int s = bx & (CSPLIT - 1); bx >>= 2;
    const int h = bx & (H_ - 1);
    const int b = bx >> 7;
    const int pix = (b * H_ + h) * W_ + w;

    const float2 o = g_off[pix];
    float px = (float)h + o.x + bc[0];
    float py = (float)w + o.y + bc[1];
    px = fminf(fmaxf(px, 0.f), (float)(H_ - 2));
    py = fminf(fmaxf(py, 0.f), (float)(W_ - 2));

    const float fx = floorf(px), fy = floorf(py);
    const float dx = px - fx,    dy = py - fy;
    const float w00 = (1.f - dx) * (1.f - dy);
    const float w01 = (1.f - dx) * dy;
    const float w10 = dx * (1.f - dy);
    const float w11 = dx * dy;

    const int qx = (int)fx, qy = (int)fy;
    const float* xp = x   + ((size_t)b * C_ + s * CPS) * HW_ + qx * W_ + qy;
    float*       op = out + ((size_t)b * C_ + s * CPS) * HW_ + h * W_ + w;

#pragma unroll 8
    for (int c = 0; c < CPS; c++) {
        const float* p = xp + c * HW_;
        const float v00 = __ldg(p);
        const float v01 = __ldg(p + 1);
        const float v10 = __ldg(p + W_);
        const float v11 = __ldg(p + W_ + 1);
        op[c * HW_] = fmaf(w00, v00, fmaf(w01, v01, fmaf(w10, v10, w11 * v11)));
    }
}

// ---------------------------------------------------------------------------
extern "C" void kernel_launch(void* const* d_in, const int* in_sizes, int n_in,
                              void* d_out, int out_size) {
    const float* x  = (const float*)d_in[0];   // [8,256,128,128]
    const float* wc = (const float*)d_in[1];   // [2,256,3,3]
    const float* bc = (const float*)d_in[2];   // [2]
    float* out = (float*)d_out;                // [8,256,128,128,1]

    conv_kernel<<<B_ * (H_ / RT) * CG16, 128>>>(x, wc);
    reduce_kernel<<<NPIX / 256, 256>>>();
    sample_kernel<<<B_ * H_ * CSPLIT, 128>>>(x, bc, out);
}